// round 2
// baseline (speedup 1.0000x reference)
#include <cuda_runtime.h>
#include <cuda_bf16.h>
#include <cstdint>

#define LSEQ 2048
#define EDIM 512
#define HDIM 512
#define TAGS 64
#define NEGV (-1000.0f)
#define NCTA_DIR 64

// ---------------- scratch (static device globals; no allocation) ----------------
__device__ float g_x[LSEQ * EDIM];                 // embedded input  [L,E]
__device__ float g_xg[2 * LSEQ * 4 * HDIM];        // input-gate preacts (per dir), reused by both layers
__device__ float g_h1[LSEQ * 2 * HDIM];            // layer0 output  [L,2H]
__device__ float g_h2[LSEQ * 2 * HDIM];            // layer1 output  [L,2H]
__device__ float g_feats[LSEQ * TAGS];             // emission feats [L,T]
__device__ unsigned g_bar[4 * 32];                 // spin counters: slot (layer*2+dir)*32

// ---------------- embedding gather ----------------
__global__ void embed_kernel(const int* __restrict__ sent, const float* __restrict__ emb) {
    int t = blockIdx.x;
    int v = sent[t];
    const float4* src = (const float4*)(emb + (size_t)v * EDIM);
    float4* dst = (float4*)(g_x + (size_t)t * EDIM);
    for (int i = threadIdx.x; i < EDIM / 4; i += blockDim.x) dst[i] = src[i];
}

// ---------------- C[M,N] = A[M,K] * B[N,K]^T + b1[N] + b2[N] ----------------
// 128x128 tile, 256 threads, 8x8 microtile, K-step 8, single-stage prefetch.
__global__ __launch_bounds__(256) void gemm_tn(
    const float* __restrict__ A, const float* __restrict__ B,
    const float* __restrict__ b1, const float* __restrict__ b2,
    float* __restrict__ C, int M, int N, int K)
{
    __shared__ float As[8][128];
    __shared__ float Bs[8][132];

    int tid = threadIdx.x;
    int tx = tid & 15, ty = tid >> 4;
    int lrow = tid >> 1;
    int lk = (tid & 1) * 4;

    const float* Ap = A + (size_t)(blockIdx.y * 128 + lrow) * K + lk;
    const float* Bp = B + (size_t)(blockIdx.x * 128 + lrow) * K + lk;

    float acc[8][8];
#pragma unroll
    for (int i = 0; i < 8; i++)
#pragma unroll
        for (int j = 0; j < 8; j++) acc[i][j] = 0.f;

    float4 av = *(const float4*)Ap;
    float4 bv = *(const float4*)Bp;

    for (int k0 = 0; k0 < K; k0 += 8) {
        __syncthreads();
        As[lk + 0][lrow] = av.x; As[lk + 1][lrow] = av.y;
        As[lk + 2][lrow] = av.z; As[lk + 3][lrow] = av.w;
        Bs[lk + 0][lrow] = bv.x; Bs[lk + 1][lrow] = bv.y;
        Bs[lk + 2][lrow] = bv.z; Bs[lk + 3][lrow] = bv.w;
        __syncthreads();
        if (k0 + 8 < K) {
            av = *(const float4*)(Ap + k0 + 8);
            bv = *(const float4*)(Bp + k0 + 8);
        }
#pragma unroll
        for (int kk = 0; kk < 8; kk++) {
            float a[8], b[8];
            *(float4*)&a[0] = *(const float4*)&As[kk][ty * 4];
            *(float4*)&a[4] = *(const float4*)&As[kk][ty * 4 + 64];
            *(float4*)&b[0] = *(const float4*)&Bs[kk][tx * 4];
            *(float4*)&b[4] = *(const float4*)&Bs[kk][tx * 4 + 64];
#pragma unroll
            for (int i = 0; i < 8; i++)
#pragma unroll
                for (int j = 0; j < 8; j++) acc[i][j] += a[i] * b[j];
        }
    }

#pragma unroll
    for (int j = 0; j < 8; j++) {
        int col = blockIdx.x * 128 + ((j < 4) ? tx * 4 + j : 64 + tx * 4 + (j - 4));
        float bias = b1[col] + b2[col];
#pragma unroll
        for (int i = 0; i < 8; i++) {
            int row = blockIdx.y * 128 + ((i < 4) ? ty * 4 + i : 64 + ty * 4 + (i - 4));
            C[(size_t)row * N + col] = acc[i][j] + bias;
        }
    }
}

// ---------------- one BiLSTM layer (both directions concurrently) ----------------
// grid = 128 CTAs (64 per direction), 256 threads each.
// CTA owns 8 hidden units; warp w owns unit (cid*8+w); lanes = 4 gates x 8 segments.
// w_hh weights live in registers (64 floats/thread). h exchanged via L2 + spin barrier.
__global__ __launch_bounds__(256) void lstm_layer(
    const float* __restrict__ xg,   // [2][L][4H]  (b_ih + b_hh folded in)
    const float* __restrict__ whh,  // [2][4H][H]
    float* __restrict__ hout,       // [L][2H]  fwd -> cols [0,H), bwd -> [H,2H)
    int barslot)
{
    int dir = blockIdx.x >> 6;
    int cid = blockIdx.x & 63;
    int tid = threadIdx.x;
    int w = tid >> 5, l = tid & 31;
    int gate = l >> 3, seg = l & 7;        // gate: 0=i 1=f 2=g 3=o
    int unit = cid * 8 + w;
    int row = gate * HDIM + unit;

    const float* wrow = whh + ((size_t)dir * 4 * HDIM + row) * HDIM + seg * 64;
    float wreg[64];
#pragma unroll
    for (int k = 0; k < 16; k++) {
        float4 v = *(const float4*)(wrow + k * 4);
        wreg[k * 4 + 0] = v.x; wreg[k * 4 + 1] = v.y;
        wreg[k * 4 + 2] = v.z; wreg[k * 4 + 3] = v.w;
    }

    __shared__ float hs[8 * 68];           // h_prev, pitch 68 words -> conflict-free
    for (int i = tid; i < 8 * 68; i += 256) hs[i] = 0.f;

    volatile unsigned* cnt = &g_bar[(barslot * 2 + dir) * 32];
    const float* xg_d = xg + (size_t)dir * LSEQ * 4 * HDIM;
    float* hbase = hout + (dir ? HDIM : 0);
    float c = 0.f;
    __syncthreads();

    for (int s = 0; s < LSEQ; s++) {
        int t = dir ? (LSEQ - 1 - s) : s;

        float xgv = 0.f;
        if (seg == 0) xgv = __ldg(&xg_d[(size_t)t * (4 * HDIM) + row]);

        float acc = 0.f;
#pragma unroll
        for (int kk = 0; kk < 16; kk++) {
            float4 hv = *(const float4*)&hs[seg * 68 + kk * 4];
            acc += wreg[kk * 4 + 0] * hv.x;
            acc += wreg[kk * 4 + 1] * hv.y;
            acc += wreg[kk * 4 + 2] * hv.z;
            acc += wreg[kk * 4 + 3] * hv.w;
        }
        acc += __shfl_xor_sync(0xffffffffu, acc, 1);
        acc += __shfl_xor_sync(0xffffffffu, acc, 2);
        acc += __shfl_xor_sync(0xffffffffu, acc, 4);

        float pre = acc + xgv;             // valid on seg==0 lanes (0,8,16,24)
        float act = (gate == 2) ? tanhf(pre) : 1.f / (1.f + expf(-pre));
        float ai = __shfl_sync(0xffffffffu, act, 0);
        float af = __shfl_sync(0xffffffffu, act, 8);
        float ag = __shfl_sync(0xffffffffu, act, 16);
        float ao = __shfl_sync(0xffffffffu, act, 24);

        c = af * c + ai * ag;
        float hv = ao * tanhf(c);
        if (l == 0) {
            hbase[(size_t)t * (2 * HDIM) + unit] = hv;
            __threadfence();
        }

        if (s + 1 < LSEQ) {
            __syncthreads();
            if (tid == 0) {
                atomicAdd((unsigned*)cnt, 1u);
                unsigned tgt = (unsigned)(s + 1) * NCTA_DIR;
                while (*cnt < tgt) { }
                __threadfence();
            }
            __syncthreads();
            for (int i = tid; i < HDIM; i += 256) {
                float v = __ldcg(&hbase[(size_t)t * (2 * HDIM) + i]);
                hs[(i >> 6) * 68 + (i & 63)] = v;
            }
            __syncthreads();
        }
    }
}

// ---------------- feats = tanh(h2 @ W_tag^T + b_tag) ----------------
__global__ __launch_bounds__(256) void feats_kernel(
    const float* __restrict__ Wtag, const float* __restrict__ btag)
{
    int t = blockIdx.x;
    __shared__ float hsm[2 * HDIM];
    for (int i = threadIdx.x; i < 2 * HDIM; i += 256)
        hsm[i] = g_h2[(size_t)t * 2 * HDIM + i];
    __syncthreads();

    int tag = threadIdx.x >> 2, part = threadIdx.x & 3;
    const float4* wv = (const float4*)(Wtag + (size_t)tag * 2 * HDIM + part * 256);
    const float4* hv = (const float4*)(hsm + part * 256);
    float acc = 0.f;
#pragma unroll 8
    for (int k = 0; k < 64; k++) {
        float4 a = wv[k]; float4 b = hv[k];
        acc += a.x * b.x + a.y * b.y + a.z * b.z + a.w * b.w;
    }
    acc += __shfl_xor_sync(0xffffffffu, acc, 1);
    acc += __shfl_xor_sync(0xffffffffu, acc, 2);
    if (part == 0) g_feats[t * TAGS + tag] = tanhf(acc + btag[tag]);
}

// ---------------- Viterbi: max-plus scan + backtrace, one CTA ----------------
__global__ __launch_bounds__(256) void viterbi_kernel(
    const float* __restrict__ A, float* __restrict__ out, int out_size)
{
    extern __shared__ char smraw[];
    float* As = (float*)smraw;                           // 64*65 floats (padded)
    float* delta = As + 64 * 65;                         // 2*64 floats
    unsigned char* idxs = (unsigned char*)(delta + 128); // 2048*64 bytes

    int tid = threadIdx.x;
    for (int i = tid; i < TAGS * TAGS; i += 256) {
        int j = i >> 6, p = i & 63;
        As[j * 65 + p] = A[i];
    }
    if (tid < TAGS) delta[tid] = (tid == 0) ? 0.f : NEGV;
    for (int i = LSEQ + 1 + tid; i < out_size; i += 256) out[i] = 0.f;
    __syncthreads();

    int tag = tid >> 2, part = tid & 3;
    int cur = 0;
    for (int t = 0; t < LSEQ; t++) {
        float best = -1e30f; int barg = part * 16;
        const float* Ar = &As[tag * 65];
        const float* dc = &delta[cur * 64];
#pragma unroll
        for (int p = part * 16; p < part * 16 + 16; p++) {
            float v = dc[p] + Ar[p];
            if (v > best) { best = v; barg = p; }
        }
#pragma unroll
        for (int off = 1; off <= 2; off <<= 1) {
            float ov = __shfl_xor_sync(0xffffffffu, best, off);
            int   oi = __shfl_xor_sync(0xffffffffu, barg, off);
            if (ov > best || (ov == best && oi < barg)) { best = ov; barg = oi; }
        }
        if (part == 0) {
            idxs[t * TAGS + tag] = (unsigned char)barg;
            delta[(cur ^ 1) * 64 + tag] = g_feats[t * TAGS + tag] + best;
        }
        cur ^= 1;
        __syncthreads();
    }

    if (tid == 0) {
        const float* dc = &delta[cur * 64];
        float best = -1e30f; int bi = 0;
        for (int p = 0; p < TAGS; p++) {
            float v = dc[p] + As[(TAGS - 1) * 65 + p];
            if (v > best) { best = v; bi = p; }
        }
        if (LSEQ - 1 < out_size) out[LSEQ - 1] = (float)bi;
        int tg = bi;
        for (int t = LSEQ - 1; t >= 1; t--) {
            tg = idxs[t * TAGS + tg];
            out[t - 1] = (float)tg;
        }
        if (LSEQ < out_size) out[LSEQ] = best;
    }
}

// ---------------- launch ----------------
extern "C" void kernel_launch(void* const* d_in, const int* in_sizes, int n_in,
                              void* d_out, int out_size)
{
    const int*   sent  = (const int*)d_in[0];
    const float* emb   = (const float*)d_in[1];
    const float* w_ih0 = (const float*)d_in[2];
    const float* w_hh0 = (const float*)d_in[3];
    const float* b_ih0 = (const float*)d_in[4];
    const float* b_hh0 = (const float*)d_in[5];
    const float* w_ih1 = (const float*)d_in[6];
    const float* w_hh1 = (const float*)d_in[7];
    const float* b_ih1 = (const float*)d_in[8];
    const float* b_hh1 = (const float*)d_in[9];
    const float* Wtag  = (const float*)d_in[10];
    const float* btag  = (const float*)d_in[11];
    const float* A     = (const float*)d_in[12];

    float *x, *xg, *h1, *h2;
    unsigned* bar;
    cudaGetSymbolAddress((void**)&x,  g_x);
    cudaGetSymbolAddress((void**)&xg, g_xg);
    cudaGetSymbolAddress((void**)&h1, g_h1);
    cudaGetSymbolAddress((void**)&h2, g_h2);
    cudaGetSymbolAddress((void**)&bar, g_bar);

    cudaMemsetAsync(bar, 0, 4 * 32 * sizeof(unsigned));

    embed_kernel<<<LSEQ, 128>>>(sent, emb);

    dim3 gg(16, 16);
    // layer 0 input projections (fwd, bwd), biases folded
    gemm_tn<<<gg, 256>>>(x, w_ih0,              b_ih0,        b_hh0,        xg,                    LSEQ, 4 * HDIM, EDIM);
    gemm_tn<<<gg, 256>>>(x, w_ih0 + 2048 * 512, b_ih0 + 2048, b_hh0 + 2048, xg + LSEQ * 4 * HDIM, LSEQ, 4 * HDIM, EDIM);

    lstm_layer<<<128, 256>>>(xg, w_hh0, h1, 0);

    // layer 1 input projections (K = 2H = 1024)
    gemm_tn<<<gg, 256>>>(h1, w_ih1,               b_ih1,        b_hh1,        xg,                    LSEQ, 4 * HDIM, 2 * HDIM);
    gemm_tn<<<gg, 256>>>(h1, w_ih1 + 2048 * 1024, b_ih1 + 2048, b_hh1 + 2048, xg + LSEQ * 4 * HDIM, LSEQ, 4 * HDIM, 2 * HDIM);

    lstm_layer<<<128, 256>>>(xg, w_hh1, h2, 1);

    feats_kernel<<<LSEQ, 256>>>(Wtag, btag);

    int vit_smem = 64 * 65 * 4 + 128 * 4 + LSEQ * TAGS;
    cudaFuncSetAttribute(viterbi_kernel, cudaFuncAttributeMaxDynamicSharedMemorySize, vit_smem);
    viterbi_kernel<<<1, 256, vit_smem>>>(A, (float*)d_out, out_size);
}

// round 3
// speedup vs baseline: 1.1071x; 1.1071x over previous
#include <cuda_runtime.h>
#include <cuda_bf16.h>
#include <cstdint>

#define LSEQ 2048
#define EDIM 512
#define HDIM 512
#define TAGS 64
#define NEGV (-1000.0f)
#define NCTA_DIR 32

// ---------------- scratch (static device globals; no allocation) ----------------
__device__ float g_x[LSEQ * EDIM];                 // embedded input  [L,E]
__device__ float g_xg[2 * LSEQ * 4 * HDIM];        // input-gate preacts (per dir), reused by both layers
__device__ float g_h1[LSEQ * 2 * HDIM];            // layer0 output  [L,2H]
__device__ float g_h2[LSEQ * 2 * HDIM];            // layer1 output  [L,2H]
__device__ float g_feats[LSEQ * TAGS];             // emission feats [L,T]
__device__ unsigned g_bar[4 * 32];                 // spin counters: slot (layer*2+dir)*32

// ---- L2-scope sync primitives (no membar.gpu / no CCTL.IVALL) ----
__device__ __forceinline__ void red_release_add(unsigned* p, unsigned v) {
    asm volatile("red.release.gpu.global.add.u32 [%0], %1;" :: "l"(p), "r"(v) : "memory");
}
__device__ __forceinline__ unsigned ld_acquire(const unsigned* p) {
    unsigned v;
    asm volatile("ld.acquire.gpu.global.u32 %0, [%1];" : "=r"(v) : "l"(p) : "memory");
    return v;
}
__device__ __forceinline__ void st_cg(float* p, float v) {
    asm volatile("st.global.cg.f32 [%0], %1;" :: "l"(p), "f"(v) : "memory");
}
__device__ __forceinline__ float ld_cg(const float* p) {
    float v;
    asm volatile("ld.global.cg.f32 %0, [%1];" : "=f"(v) : "l"(p));
    return v;
}

// ---------------- embedding gather ----------------
__global__ void embed_kernel(const int* __restrict__ sent, const float* __restrict__ emb) {
    int t = blockIdx.x;
    int v = sent[t];
    const float4* src = (const float4*)(emb + (size_t)v * EDIM);
    float4* dst = (float4*)(g_x + (size_t)t * EDIM);
    for (int i = threadIdx.x; i < EDIM / 4; i += blockDim.x) dst[i] = src[i];
}

// ---------------- C[M,N] = A[M,K] * B[N,K]^T + b1[N] + b2[N] ----------------
__global__ __launch_bounds__(256) void gemm_tn(
    const float* __restrict__ A, const float* __restrict__ B,
    const float* __restrict__ b1, const float* __restrict__ b2,
    float* __restrict__ C, int M, int N, int K)
{
    __shared__ float As[8][128];
    __shared__ float Bs[8][132];

    int tid = threadIdx.x;
    int tx = tid & 15, ty = tid >> 4;
    int lrow = tid >> 1;
    int lk = (tid & 1) * 4;

    const float* Ap = A + (size_t)(blockIdx.y * 128 + lrow) * K + lk;
    const float* Bp = B + (size_t)(blockIdx.x * 128 + lrow) * K + lk;

    float acc[8][8];
#pragma unroll
    for (int i = 0; i < 8; i++)
#pragma unroll
        for (int j = 0; j < 8; j++) acc[i][j] = 0.f;

    float4 av = *(const float4*)Ap;
    float4 bv = *(const float4*)Bp;

    for (int k0 = 0; k0 < K; k0 += 8) {
        __syncthreads();
        As[lk + 0][lrow] = av.x; As[lk + 1][lrow] = av.y;
        As[lk + 2][lrow] = av.z; As[lk + 3][lrow] = av.w;
        Bs[lk + 0][lrow] = bv.x; Bs[lk + 1][lrow] = bv.y;
        Bs[lk + 2][lrow] = bv.z; Bs[lk + 3][lrow] = bv.w;
        __syncthreads();
        if (k0 + 8 < K) {
            av = *(const float4*)(Ap + k0 + 8);
            bv = *(const float4*)(Bp + k0 + 8);
        }
#pragma unroll
        for (int kk = 0; kk < 8; kk++) {
            float a[8], b[8];
            *(float4*)&a[0] = *(const float4*)&As[kk][ty * 4];
            *(float4*)&a[4] = *(const float4*)&As[kk][ty * 4 + 64];
            *(float4*)&b[0] = *(const float4*)&Bs[kk][tx * 4];
            *(float4*)&b[4] = *(const float4*)&Bs[kk][tx * 4 + 64];
#pragma unroll
            for (int i = 0; i < 8; i++)
#pragma unroll
                for (int j = 0; j < 8; j++) acc[i][j] += a[i] * b[j];
        }
    }

#pragma unroll
    for (int j = 0; j < 8; j++) {
        int col = blockIdx.x * 128 + ((j < 4) ? tx * 4 + j : 64 + tx * 4 + (j - 4));
        float bias = b1[col] + b2[col];
#pragma unroll
        for (int i = 0; i < 8; i++) {
            int row = blockIdx.y * 128 + ((i < 4) ? ty * 4 + i : 64 + ty * 4 + (i - 4));
            C[(size_t)row * N + col] = acc[i][j] + bias;
        }
    }
}

// ---------------- one BiLSTM layer (both directions concurrently) ----------------
// grid = 64 CTAs (32 per direction), 512 threads each.
// CTA owns 16 hidden units; warp w owns unit (cid*16+w); lanes = 4 gates x 8 segments.
// w_hh in registers (64 floats/thread). h exchanged via L2 with release/acquire.
__global__ __launch_bounds__(512) void lstm_layer(
    const float* __restrict__ xg,   // [2][L][4H]  (b_ih + b_hh folded in)
    const float* __restrict__ whh,  // [2][4H][H]
    float* __restrict__ hout,       // [L][2H]  fwd -> cols [0,H), bwd -> [H,2H)
    int barslot)
{
    int dir = blockIdx.x >> 5;
    int cid = blockIdx.x & 31;
    int tid = threadIdx.x;
    int w = tid >> 5, l = tid & 31;
    int gate = l >> 3, seg = l & 7;        // gate: 0=i 1=f 2=g 3=o
    int unit = cid * 16 + w;
    int row = gate * HDIM + unit;

    const float* wrow = whh + ((size_t)dir * 4 * HDIM + row) * HDIM + seg * 64;
    float wreg[64];
#pragma unroll
    for (int k = 0; k < 16; k++) {
        float4 v = *(const float4*)(wrow + k * 4);
        wreg[k * 4 + 0] = v.x; wreg[k * 4 + 1] = v.y;
        wreg[k * 4 + 2] = v.z; wreg[k * 4 + 3] = v.w;
    }

    __shared__ float hs[8 * 68];           // h_prev, pitch 68 words -> conflict-free
    for (int i = tid; i < 8 * 68; i += 512) hs[i] = 0.f;

    unsigned* cnt = &g_bar[(barslot * 2 + dir) * 32];
    const float* xg_d = xg + (size_t)dir * LSEQ * 4 * HDIM;
    float* hbase = hout + (dir ? HDIM : 0);
    float c = 0.f;
    __syncthreads();

    int t0 = dir ? (LSEQ - 1) : 0;
    float xgv = 0.f;
    if (seg == 0) xgv = ld_cg(&xg_d[(size_t)t0 * (4 * HDIM) + row]);

    for (int s = 0; s < LSEQ; s++) {
        int t = dir ? (LSEQ - 1 - s) : s;

        float acc = 0.f;
#pragma unroll
        for (int kk = 0; kk < 16; kk++) {
            float4 hv = *(const float4*)&hs[seg * 68 + kk * 4];
            acc += wreg[kk * 4 + 0] * hv.x;
            acc += wreg[kk * 4 + 1] * hv.y;
            acc += wreg[kk * 4 + 2] * hv.z;
            acc += wreg[kk * 4 + 3] * hv.w;
        }
        acc += __shfl_xor_sync(0xffffffffu, acc, 1);
        acc += __shfl_xor_sync(0xffffffffu, acc, 2);
        acc += __shfl_xor_sync(0xffffffffu, acc, 4);

        float pre = acc + xgv;             // valid on seg==0 lanes (0,8,16,24)
        float act = (gate == 2) ? tanhf(pre) : 1.f / (1.f + expf(-pre));
        float ai = __shfl_sync(0xffffffffu, act, 0);
        float af = __shfl_sync(0xffffffffu, act, 8);
        float ag = __shfl_sync(0xffffffffu, act, 16);
        float ao = __shfl_sync(0xffffffffu, act, 24);

        c = af * c + ai * ag;
        float hv = ao * tanhf(c);
        if (l == 0) st_cg(&hbase[(size_t)t * (2 * HDIM) + unit], hv);

        if (s + 1 < LSEQ) {
            __syncthreads();                        // all warps' h stores issued (CTA scope)
            if (tid == 0) red_release_add(cnt, 1u); // publishes whole CTA's stores

            int tn = dir ? (LSEQ - 2 - s) : (s + 1);
            if (seg == 0) xgv = ld_cg(&xg_d[(size_t)tn * (4 * HDIM) + row]);  // prefetch under spin

            unsigned tgt = (unsigned)(s + 1) * NCTA_DIR;
            while (ld_acquire(cnt) < tgt) { }

            // refill h_prev: 512 threads, one float each, L2-coherent
            {
                float v = ld_cg(&hbase[(size_t)t * (2 * HDIM) + tid]);
                hs[(tid >> 6) * 68 + (tid & 63)] = v;
            }
            __syncthreads();
        }
    }
}

// ---------------- feats = tanh(h2 @ W_tag^T + b_tag) ----------------
__global__ __launch_bounds__(256) void feats_kernel(
    const float* __restrict__ Wtag, const float* __restrict__ btag)
{
    int t = blockIdx.x;
    __shared__ float hsm[2 * HDIM];
    for (int i = threadIdx.x; i < 2 * HDIM; i += 256)
        hsm[i] = g_h2[(size_t)t * 2 * HDIM + i];
    __syncthreads();

    int tag = threadIdx.x >> 2, part = threadIdx.x & 3;
    const float4* wv = (const float4*)(Wtag + (size_t)tag * 2 * HDIM + part * 256);
    const float4* hv = (const float4*)(hsm + part * 256);
    float acc = 0.f;
#pragma unroll 8
    for (int k = 0; k < 64; k++) {
        float4 a = wv[k]; float4 b = hv[k];
        acc += a.x * b.x + a.y * b.y + a.z * b.z + a.w * b.w;
    }
    acc += __shfl_xor_sync(0xffffffffu, acc, 1);
    acc += __shfl_xor_sync(0xffffffffu, acc, 2);
    if (part == 0) g_feats[t * TAGS + tag] = tanhf(acc + btag[tag]);
}

// ---------------- Viterbi: max-plus scan + backtrace, one CTA ----------------
__global__ __launch_bounds__(256) void viterbi_kernel(
    const float* __restrict__ A, float* __restrict__ out, int out_size)
{
    extern __shared__ char smraw[];
    float* As = (float*)smraw;                           // 64*65 floats (padded)
    float* delta = As + 64 * 65;                         // 2*64 floats
    unsigned char* idxs = (unsigned char*)(delta + 128); // 2048*64 bytes

    int tid = threadIdx.x;
    for (int i = tid; i < TAGS * TAGS; i += 256) {
        int j = i >> 6, p = i & 63;
        As[j * 65 + p] = A[i];
    }
    if (tid < TAGS) delta[tid] = (tid == 0) ? 0.f : NEGV;
    for (int i = LSEQ + 1 + tid; i < out_size; i += 256) out[i] = 0.f;
    __syncthreads();

    int tag = tid >> 2, part = tid & 3;
    int cur = 0;
    for (int t = 0; t < LSEQ; t++) {
        float best = -1e30f; int barg = part * 16;
        const float* Ar = &As[tag * 65];
        const float* dc = &delta[cur * 64];
#pragma unroll
        for (int p = part * 16; p < part * 16 + 16; p++) {
            float v = dc[p] + Ar[p];
            if (v > best) { best = v; barg = p; }
        }
#pragma unroll
        for (int off = 1; off <= 2; off <<= 1) {
            float ov = __shfl_xor_sync(0xffffffffu, best, off);
            int   oi = __shfl_xor_sync(0xffffffffu, barg, off);
            if (ov > best || (ov == best && oi < barg)) { best = ov; barg = oi; }
        }
        if (part == 0) {
            idxs[t * TAGS + tag] = (unsigned char)barg;
            delta[(cur ^ 1) * 64 + tag] = g_feats[t * TAGS + tag] + best;
        }
        cur ^= 1;
        __syncthreads();
    }

    if (tid == 0) {
        const float* dc = &delta[cur * 64];
        float best = -1e30f; int bi = 0;
        for (int p = 0; p < TAGS; p++) {
            float v = dc[p] + As[(TAGS - 1) * 65 + p];
            if (v > best) { best = v; bi = p; }
        }
        if (LSEQ - 1 < out_size) out[LSEQ - 1] = (float)bi;
        int tg = bi;
        for (int t = LSEQ - 1; t >= 1; t--) {
            tg = idxs[t * TAGS + tg];
            out[t - 1] = (float)tg;
        }
        if (LSEQ < out_size) out[LSEQ] = best;
    }
}

// ---------------- launch ----------------
extern "C" void kernel_launch(void* const* d_in, const int* in_sizes, int n_in,
                              void* d_out, int out_size)
{
    const int*   sent  = (const int*)d_in[0];
    const float* emb   = (const float*)d_in[1];
    const float* w_ih0 = (const float*)d_in[2];
    const float* w_hh0 = (const float*)d_in[3];
    const float* b_ih0 = (const float*)d_in[4];
    const float* b_hh0 = (const float*)d_in[5];
    const float* w_ih1 = (const float*)d_in[6];
    const float* w_hh1 = (const float*)d_in[7];
    const float* b_ih1 = (const float*)d_in[8];
    const float* b_hh1 = (const float*)d_in[9];
    const float* Wtag  = (const float*)d_in[10];
    const float* btag  = (const float*)d_in[11];
    const float* A     = (const float*)d_in[12];

    float *x, *xg, *h1, *h2;
    unsigned* bar;
    cudaGetSymbolAddress((void**)&x,  g_x);
    cudaGetSymbolAddress((void**)&xg, g_xg);
    cudaGetSymbolAddress((void**)&h1, g_h1);
    cudaGetSymbolAddress((void**)&h2, g_h2);
    cudaGetSymbolAddress((void**)&bar, g_bar);

    cudaMemsetAsync(bar, 0, 4 * 32 * sizeof(unsigned));

    embed_kernel<<<LSEQ, 128>>>(sent, emb);

    dim3 gg(16, 16);
    // layer 0 input projections (fwd, bwd), biases folded
    gemm_tn<<<gg, 256>>>(x, w_ih0,              b_ih0,        b_hh0,        xg,                    LSEQ, 4 * HDIM, EDIM);
    gemm_tn<<<gg, 256>>>(x, w_ih0 + 2048 * 512, b_ih0 + 2048, b_hh0 + 2048, xg + LSEQ * 4 * HDIM, LSEQ, 4 * HDIM, EDIM);

    lstm_layer<<<64, 512>>>(xg, w_hh0, h1, 0);

    // layer 1 input projections (K = 2H = 1024)
    gemm_tn<<<gg, 256>>>(h1, w_ih1,               b_ih1,        b_hh1,        xg,                    LSEQ, 4 * HDIM, 2 * HDIM);
    gemm_tn<<<gg, 256>>>(h1, w_ih1 + 2048 * 1024, b_ih1 + 2048, b_hh1 + 2048, xg + LSEQ * 4 * HDIM, LSEQ, 4 * HDIM, 2 * HDIM);

    lstm_layer<<<64, 512>>>(xg, w_hh1, h2, 1);

    feats_kernel<<<LSEQ, 256>>>(Wtag, btag);

    int vit_smem = 64 * 65 * 4 + 128 * 4 + LSEQ * TAGS;
    cudaFuncSetAttribute(viterbi_kernel, cudaFuncAttributeMaxDynamicSharedMemorySize, vit_smem);
    viterbi_kernel<<<1, 256, vit_smem>>>(A, (float*)d_out, out_size);
}